// round 10
// baseline (speedup 1.0000x reference)
#include <cuda_runtime.h>
#include <math.h>

#define BB 32
#define TT 1024
#define VV 5000
#define STEPS 64
#define JPAD 5008
#define NP 32            // attention T-parts
#define TCH 32           // t-chunk per part
#define TS 132           // tile stride
#define LJT 157          // logits j-tiles of 32
#define LKS 4            // logits K-split
#define NB 592           // persistent blocks = 4 * 148
#define NGRP 37          // barrier groups (592 = 37*16)

// ---------------- persistent device state ----------------
__device__ float g_xT[512 * BB];             // emb(tok) transposed [k][b]
__device__ float g_hcT[1024 * BB];           // [h|ctx] transposed [k][b]
__device__ float g_hRow[BB * 512];           // h row-major
__device__ float g_cT[512 * BB];             // cell state [i][b]
__device__ float g_hhP[2048 * BB];           // W_hh @ h partial [j][b]
__device__ float g_cxP[2048 * BB];           // W_ih_ctx @ ctx partial [j][b]
__device__ float g_hidT[512 * BB];
__device__ float g_logitsP[LKS][BB * JPAD];
__device__ float g_eBuf[BB * TT];
__device__ float g_mP[NP * 128];
__device__ float g_sP[NP * 128];
__device__ float g_ctxP[NP][128 * 128];

// ---------------- hierarchical grid barrier (monotonic) ----------------
__device__ unsigned g_grp[NGRP * 32];        // group counters, padded
__device__ unsigned g_root;
__device__ unsigned g_gen;

__device__ __forceinline__ void grid_sync(unsigned target)
{
    __syncthreads();
    if (threadIdx.x == 0) {
        __threadfence();
        unsigned grp = blockIdx.x >> 4;
        unsigned o = atomicAdd(&g_grp[grp * 32], 1u);
        if ((o & 15u) == 15u) {                     // last of this group, this round
            unsigned r = atomicAdd(&g_root, 1u);
            if (r % NGRP == NGRP - 1u) {            // last group
                __threadfence();
                atomicExch(&g_gen, target);
            }
        }
        volatile unsigned* vg = &g_gen;
        while (*vg != target) __nanosleep(32);
        __threadfence();
    }
    __syncthreads();
}

// =================== the whole decode in ONE kernel ===================
__global__ void __launch_bounds__(256, 4)
decode_kernel(const float* __restrict__ lf,   const float* __restrict__ emb,
              const float* __restrict__ W_ih, const float* __restrict__ W_hh,
              const float* __restrict__ b_ih, const float* __restrict__ b_hh,
              const float* __restrict__ Wp,   const float* __restrict__ bp,
              const float* __restrict__ Wc,   const float* __restrict__ bc,
              float* __restrict__ out_pred,   float* __restrict__ out_attn)
{
    __shared__ __align__(16) float s_f[6176];
    const int tid = threadIdx.x;

    unsigned gen = g_gen;
    unsigned bk = 0;

    // ---- init 0a: xT = emb[0]; hcT ctx-slot = lf[:,0,:]; c = 0; hhP = 0 ----
    for (int idx = blockIdx.x * 256 + tid; idx < 512 * BB; idx += NB * 256) {
        int b = idx & 31, kk = idx >> 5;
        g_xT[idx] = emb[kk];
        g_hcT[(512 + kk) * 32 + b] = lf[(size_t)b * TT * 512 + kk];
        g_cT[idx] = 0.f;
    }
    for (int idx = blockIdx.x * 256 + tid; idx < 2048 * BB; idx += NB * 256)
        g_hhP[idx] = 0.f;
    grid_sync(gen + (++bk));

    // ---- init 0b: cxP = W_ih[:,512:] @ lf0 (128 tiles) ----
    {
        float* s_k1 = s_f;
        for (int vb = blockIdx.x; vb < 128; vb += NB) {
            int j0 = vb * 16;
            int bg = tid & 7, jj = (tid >> 3) & 15, kh = tid >> 7;
            int j = j0 + jj;
            const float* wr = W_ih + (size_t)j * 1024 + 512 + kh * 256;
            const float4* xv = (const float4*)g_hcT + (512 + kh * 256) * 8;
            float4 a = make_float4(0.f, 0.f, 0.f, 0.f);
            #pragma unroll 8
            for (int kk = 0; kk < 256; kk++) {
                float w = wr[kk];
                float4 x = xv[kk * 8 + bg];
                a.x = fmaf(w, x.x, a.x); a.y = fmaf(w, x.y, a.y);
                a.z = fmaf(w, x.z, a.z); a.w = fmaf(w, x.w, a.w);
            }
            if (kh == 1) ((float4*)s_k1)[jj * 8 + bg] = a;
            __syncthreads();
            if (kh == 0) {
                float4 o = ((float4*)s_k1)[jj * 8 + bg];
                a.x += o.x; a.y += o.y; a.z += o.z; a.w += o.w;
                ((float4*)g_cxP)[j * 8 + bg] = a;
            }
            __syncthreads();
        }
    }
    grid_sync(gen + (++bk));

    for (int s = 0; s < STEPS; s++) {
        // ===== P1: emb-gates (K=512) + partials + fused LSTM pointwise (128 tiles) =====
        {
            float* s_k1 = s_f;            // 512 floats (16*8 float4)
            float* s_g  = s_f + 512;      // 16*33
            for (int ig = blockIdx.x; ig < 128; ig += NB) {
                int bg = tid & 7, jj = (tid >> 3) & 15, kh = tid >> 7;
                int gate = jj >> 2, il = jj & 3;
                int j = gate * 512 + ig * 4 + il;
                const float* wr = W_ih + (size_t)j * 1024 + kh * 256;
                const float4* xv = (const float4*)g_xT + kh * 256 * 8;
                float4 a = make_float4(0.f, 0.f, 0.f, 0.f);
                #pragma unroll 8
                for (int kk = 0; kk < 256; kk++) {
                    float w = wr[kk];
                    float4 x = xv[kk * 8 + bg];
                    a.x = fmaf(w, x.x, a.x); a.y = fmaf(w, x.y, a.y);
                    a.z = fmaf(w, x.z, a.z); a.w = fmaf(w, x.w, a.w);
                }
                if (kh == 1) ((float4*)s_k1)[jj * 8 + bg] = a;
                __syncthreads();
                if (kh == 0) {
                    float4 o  = ((float4*)s_k1)[jj * 8 + bg];
                    float4 hh = ((const float4*)g_hhP)[j * 8 + bg];
                    float4 cx = ((const float4*)g_cxP)[j * 8 + bg];
                    float bias = b_ih[j] + b_hh[j];
                    int b0 = bg * 4;
                    s_g[jj * 33 + b0 + 0] = a.x + o.x + hh.x + cx.x + bias;
                    s_g[jj * 33 + b0 + 1] = a.y + o.y + hh.y + cx.y + bias;
                    s_g[jj * 33 + b0 + 2] = a.z + o.z + hh.z + cx.z + bias;
                    s_g[jj * 33 + b0 + 3] = a.w + o.w + hh.w + cx.w + bias;
                }
                __syncthreads();
                if (tid < 128) {
                    int il2 = tid >> 5, b = tid & 31;
                    int i = ig * 4 + il2;
                    float gi = s_g[(0  + il2) * 33 + b];
                    float gf = s_g[(4  + il2) * 33 + b];
                    float gg = s_g[(8  + il2) * 33 + b];
                    float go = s_g[(12 + il2) * 33 + b];
                    float si = 1.f / (1.f + __expf(-gi));
                    float sf = 1.f / (1.f + __expf(-gf));
                    float so = 1.f / (1.f + __expf(-go));
                    float tg = tanhf(gg);
                    float c = sf * g_cT[i * 32 + b] + si * tg;
                    g_cT[i * 32 + b] = c;
                    float h = so * tanhf(c);
                    g_hRow[b * 512 + i] = h;
                    g_hcT[i * 32 + b] = h;
                }
                __syncthreads();
            }
        }
        grid_sync(gen + (++bk));

        // ===== P2: attention partials (4096 tiles) =====
        {
            float* tile = s_f;                     // 32*132
            float* ds_s = s_f + 4224;              // 128
            float* ep   = s_f + 4352;              // 8*32
            float* csh  = s_f + 4608;              // 8*132
            float* e_s  = s_f + 5664;              // 32
            for (int vb = blockIdx.x; vb < 128 * NP; vb += NB) {
                int b = vb & 31, hh = (vb >> 5) & 3, part = vb >> 7;
                int t0 = part * TCH;
                if (tid < 128) ds_s[tid] = g_hRow[b * 512 + hh * 128 + tid];
                const float4* src = (const float4*)(lf + ((size_t)b * TT + t0) * 512 + hh * 128);
                #pragma unroll
                for (int it = 0; it < 4; it++) {
                    int idx = tid + it * 256;
                    int t = idx >> 5, c = idx & 31;
                    ((float4*)&tile[t * TS])[c] = src[(size_t)t * 128 + c];
                }
                __syncthreads();
                {
                    int t = tid & 31, dg = tid >> 5;
                    const float4* tr = (const float4*)&tile[t * TS + dg * 16];
                    const float4* dsp = (const float4*)&ds_s[dg * 16];
                    float a = 0.f;
                    #pragma unroll
                    for (int i = 0; i < 4; i++) {
                        float4 v = tr[i], d = dsp[i];
                        a = fmaf(d.x, v.x, a); a = fmaf(d.y, v.y, a);
                        a = fmaf(d.z, v.z, a); a = fmaf(d.w, v.w, a);
                    }
                    ep[dg * TCH + t] = a;
                }
                __syncthreads();
                int bh = b * 4 + hh;
                if (tid < TCH) {
                    float e = ep[tid];
                    #pragma unroll
                    for (int q = 1; q < 8; q++) e += ep[q * TCH + tid];
                    if (hh == 3) g_eBuf[b * TT + t0 + tid] = e;
                    float m = e;
                    #pragma unroll
                    for (int off = 16; off; off >>= 1) m = fmaxf(m, __shfl_xor_sync(~0u, m, off));
                    float p = __expf(e - m);
                    e_s[tid] = p;
                    float ss = p;
                    #pragma unroll
                    for (int off = 16; off; off >>= 1) ss += __shfl_xor_sync(~0u, ss, off);
                    if (tid == 0) { g_mP[part * 128 + bh] = m; g_sP[part * 128 + bh] = ss; }
                }
                __syncthreads();
                {
                    int dq = tid & 31, tg = tid >> 5;
                    float4 acc = make_float4(0.f, 0.f, 0.f, 0.f);
                    #pragma unroll
                    for (int i = 0; i < 4; i++) {
                        int t = tg * 4 + i;
                        float p = e_s[t];
                        float4 v = *(const float4*)&tile[t * TS + dq * 4];
                        acc.x = fmaf(p, v.x, acc.x); acc.y = fmaf(p, v.y, acc.y);
                        acc.z = fmaf(p, v.z, acc.z); acc.w = fmaf(p, v.w, acc.w);
                    }
                    ((float4*)&csh[tg * TS])[dq] = acc;
                }
                __syncthreads();
                if (tid < 128) {
                    float ss = 0.f;
                    #pragma unroll
                    for (int tg = 0; tg < 8; tg++) ss += csh[tg * TS + tid];
                    g_ctxP[part][bh * 128 + tid] = ss;
                }
                __syncthreads();
            }
        }
        grid_sync(gen + (++bk));

        // ===== P3: attention combine (128 tiles) =====
        {
            float* w_s = s_f;
            float* MsSs = s_f + 32;
            float* attn_row = out_attn + (size_t)s * BB * TT;
            for (int vb = blockIdx.x; vb < 128; vb += NB) {
                int b = vb & 31, hh = vb >> 5;
                int bh = b * 4 + hh;
                if (tid < 32) {
                    float m = g_mP[tid * 128 + bh];
                    float sp = g_sP[tid * 128 + bh];
                    float M = m;
                    #pragma unroll
                    for (int off = 16; off; off >>= 1) M = fmaxf(M, __shfl_xor_sync(~0u, M, off));
                    float w = __expf(m - M);
                    w_s[tid] = w;
                    float ss = sp * w;
                    #pragma unroll
                    for (int off = 16; off; off >>= 1) ss += __shfl_xor_sync(~0u, ss, off);
                    if (tid == 0) { MsSs[0] = M; MsSs[1] = ss; }
                }
                __syncthreads();
                float inv = 1.f / MsSs[1];
                float M = MsSs[0];
                if (tid < 128) {
                    float ctx = 0.f;
                    #pragma unroll
                    for (int p = 0; p < NP; p++) ctx = fmaf(g_ctxP[p][bh * 128 + tid], w_s[p], ctx);
                    ctx *= inv;
                    g_hcT[(512 + hh * 128 + tid) * 32 + b] = ctx;
                    if (hh == 3) {
                        #pragma unroll
                        for (int i = 0; i < 8; i++) {
                            int t = tid + i * 128;
                            __stcs(&attn_row[(size_t)b * TT + t], __expf(g_eBuf[b * TT + t] - M) * inv);
                        }
                    }
                }
                __syncthreads();
            }
        }
        grid_sync(gen + (++bk));

        // ===== P4: hid (128) + W_hh@h gate partials (128) = 256 tiles =====
        {
            float* ph = s_f;      // hid scratch 8*32
            float* s_k1 = s_f;    // hh scratch 512 (branches exclusive per block-iteration)
            for (int vb = blockIdx.x; vb < 256; vb += NB) {
                if (vb < 128) {
                    int wid = tid >> 5, lane = tid & 31;
                    int jj = wid >> 1, half = wid & 1;
                    int j = vb * 4 + jj;
                    const float4* wv = (const float4*)(Wp + (size_t)j * 1024 + half * 512);
                    const float* x = g_hcT + half * 512 * BB;
                    float acc = 0.f;
                    #pragma unroll 8
                    for (int k4 = 0; k4 < 128; k4++) {
                        float4 wq = wv[k4];
                        int kk = k4 * 4;
                        acc = fmaf(wq.x, x[(kk + 0) * BB + lane], acc);
                        acc = fmaf(wq.y, x[(kk + 1) * BB + lane], acc);
                        acc = fmaf(wq.z, x[(kk + 2) * BB + lane], acc);
                        acc = fmaf(wq.w, x[(kk + 3) * BB + lane], acc);
                    }
                    ph[wid * 32 + lane] = acc;
                    __syncthreads();
                    if (wid < 4) {
                        int j2 = vb * 4 + wid;
                        float v = ph[wid * 64 + lane] + ph[wid * 64 + 32 + lane] + bp[j2];
                        g_hidT[j2 * BB + lane] = fmaxf(v, 0.f);
                    }
                    __syncthreads();
                } else {
                    int j0 = (vb - 128) * 16;
                    int bg = tid & 7, jj = (tid >> 3) & 15, kh = tid >> 7;
                    int j = j0 + jj;
                    const float* wr = W_hh + (size_t)j * 512 + kh * 256;
                    const float4* xv = (const float4*)g_hcT + kh * 256 * 8;
                    float4 a = make_float4(0.f, 0.f, 0.f, 0.f);
                    #pragma unroll 8
                    for (int kk = 0; kk < 256; kk++) {
                        float w = wr[kk];
                        float4 x = xv[kk * 8 + bg];
                        a.x = fmaf(w, x.x, a.x); a.y = fmaf(w, x.y, a.y);
                        a.z = fmaf(w, x.z, a.z); a.w = fmaf(w, x.w, a.w);
                    }
                    if (kh == 1) ((float4*)s_k1)[jj * 8 + bg] = a;
                    __syncthreads();
                    if (kh == 0) {
                        float4 o = ((float4*)s_k1)[jj * 8 + bg];
                        a.x += o.x; a.y += o.y; a.z += o.z; a.w += o.w;
                        ((float4*)g_hhP)[j * 8 + bg] = a;
                    }
                    __syncthreads();
                }
            }
        }
        grid_sync(gen + (++bk));

        // ===== P5: logits (628) + W_ih_ctx@ctx gate partials (128) = 756 tiles =====
        {
            float* ws = s_f;      // 32*129
            float* s_k1 = s_f;    // 512
            for (int vb = blockIdx.x; vb < LJT * LKS + 128; vb += NB) {
                if (vb < LJT * LKS) {
                    int jt = vb % LJT, part = vb / LJT;
                    int j0 = jt * 32, base = part * 128;
                    for (int idx = tid; idx < 32 * 128; idx += 256) {
                        int r = idx >> 7, kk = idx & 127;
                        int j = j0 + r;
                        ws[r * 129 + kk] = (j < VV) ? Wc[(size_t)j * 512 + base + kk] : 0.f;
                    }
                    __syncthreads();
                    int bg = tid & 7, jj = tid >> 3;
                    int j = j0 + jj;
                    const float* wr = ws + jj * 129;
                    const float4* xv = (const float4*)g_hidT;
                    float ax = 0.f, ay = 0.f, az = 0.f, aw = 0.f;
                    #pragma unroll 8
                    for (int kk = 0; kk < 128; kk++) {
                        float w = wr[kk];
                        float4 x = xv[(base + kk) * 8 + bg];
                        ax = fmaf(w, x.x, ax); ay = fmaf(w, x.y, ay);
                        az = fmaf(w, x.z, az); aw = fmaf(w, x.w, aw);
                    }
                    if (j < VV) {
                        float* dst = g_logitsP[part];
                        int b0 = bg * 4;
                        dst[(size_t)(b0 + 0) * JPAD + j] = ax;
                        dst[(size_t)(b0 + 1) * JPAD + j] = ay;
                        dst[(size_t)(b0 + 2) * JPAD + j] = az;
                        dst[(size_t)(b0 + 3) * JPAD + j] = aw;
                    }
                    __syncthreads();
                } else {
                    int j0 = (vb - LJT * LKS) * 16;
                    int bg = tid & 7, jj = (tid >> 3) & 15, kh = tid >> 7;
                    int j = j0 + jj;
                    const float* wr = W_ih + (size_t)j * 1024 + 512 + kh * 256;
                    const float4* xv = (const float4*)g_hcT + (512 + kh * 256) * 8;
                    float4 a = make_float4(0.f, 0.f, 0.f, 0.f);
                    #pragma unroll 8
                    for (int kk = 0; kk < 256; kk++) {
                        float w = wr[kk];
                        float4 x = xv[kk * 8 + bg];
                        a.x = fmaf(w, x.x, a.x); a.y = fmaf(w, x.y, a.y);
                        a.z = fmaf(w, x.z, a.z); a.w = fmaf(w, x.w, a.w);
                    }
                    if (kh == 1) ((float4*)s_k1)[jj * 8 + bg] = a;
                    __syncthreads();
                    if (kh == 0) {
                        float4 o = ((float4*)s_k1)[jj * 8 + bg];
                        a.x += o.x; a.y += o.y; a.z += o.z; a.w += o.w;
                        ((float4*)g_cxP)[j * 8 + bg] = a;
                    }
                    __syncthreads();
                }
            }
        }
        grid_sync(gen + (++bk));

        // ===== P6: log_softmax + argmax + feedback (32 tiles) =====
        {
            float* v_s = s_f;                 // 5000
            float* sv  = s_f + 5000;          // 256
            int*   si  = (int*)(s_f + 5256);  // 256
            int*   tok_s = (int*)(s_f + 5512);
            float* pred_row = out_pred + (size_t)s * BB * VV;
            for (int vb = blockIdx.x; vb < 32; vb += NB) {
                int b = vb;
                const float4* p0 = (const float4*)(g_logitsP[0] + (size_t)b * JPAD);
                const float4* p1 = (const float4*)(g_logitsP[1] + (size_t)b * JPAD);
                const float4* p2 = (const float4*)(g_logitsP[2] + (size_t)b * JPAD);
                const float4* p3 = (const float4*)(g_logitsP[3] + (size_t)b * JPAD);
                const float4* bcv = (const float4*)bc;
                for (int j4 = tid; j4 < VV / 4; j4 += 256) {
                    float4 a = p0[j4], c = p1[j4], d = p2[j4], e = p3[j4], f = bcv[j4];
                    float4 r;
                    r.x = a.x + c.x + d.x + e.x + f.x;
                    r.y = a.y + c.y + d.y + e.y + f.y;
                    r.z = a.z + c.z + d.z + e.z + f.z;
                    r.w = a.w + c.w + d.w + e.w + f.w;
                    ((float4*)v_s)[j4] = r;
                }
                __syncthreads();

                float m = -1e30f; int mi = VV;
                for (int j = tid; j < VV; j += 256) {
                    float v = v_s[j];
                    if (v > m) { m = v; mi = j; }
                }
                sv[tid] = m; si[tid] = mi; __syncthreads();
                for (int st = 128; st; st >>= 1) {
                    if (tid < st) {
                        float v2 = sv[tid + st]; int i2 = si[tid + st];
                        if (v2 > sv[tid] || (v2 == sv[tid] && i2 < si[tid])) { sv[tid] = v2; si[tid] = i2; }
                    }
                    __syncthreads();
                }
                float mm = sv[0];
                if (tid == 0) *tok_s = si[0];
                __syncthreads();

                float ssum = 0.f;
                for (int j = tid; j < VV; j += 256) ssum += __expf(v_s[j] - mm);
                sv[tid] = ssum; __syncthreads();
                for (int st = 128; st; st >>= 1) {
                    if (tid < st) sv[tid] += sv[tid + st];
                    __syncthreads();
                }
                float lse = mm + logf(sv[0]);

                float4* row = (float4*)(pred_row + (size_t)b * VV);
                for (int j4 = tid; j4 < VV / 4; j4 += 256) {
                    float4 v = ((float4*)v_s)[j4];
                    v.x -= lse; v.y -= lse; v.z -= lse; v.w -= lse;
                    __stcs(&row[j4], v);
                }

                int tok = *tok_s;
                for (int kk = tid; kk < 512; kk += 256)
                    g_xT[kk * BB + b] = emb[(size_t)tok * 512 + kk];
                __syncthreads();
            }
        }
        grid_sync(gen + (++bk));
    }
}

// ---------------- launcher ----------------
extern "C" void kernel_launch(void* const* d_in, const int* in_sizes, int n_in,
                              void* d_out, int out_size)
{
    const float* lf   = (const float*)d_in[0];
    const float* emb  = (const float*)d_in[1];
    const float* W_ih = (const float*)d_in[2];
    const float* W_hh = (const float*)d_in[3];
    const float* b_ih = (const float*)d_in[4];
    const float* b_hh = (const float*)d_in[5];
    const float* Wp   = (const float*)d_in[6];
    const float* bp   = (const float*)d_in[7];
    const float* Wc   = (const float*)d_in[8];
    const float* bc   = (const float*)d_in[9];

    float* out      = (float*)d_out;
    float* out_pred = out;
    float* out_attn = out + (size_t)STEPS * BB * VV;

    decode_kernel<<<NB, 256>>>(lf, emb, W_ih, W_hh, b_ih, b_hh,
                               Wp, bp, Wc, bc, out_pred, out_attn);
}